// round 17
// baseline (speedup 1.0000x reference)
#include <cuda_runtime.h>
#include <cuda_bf16.h>
#include <math.h>

// Problem constants
#define kN 4
#define kH 96
#define kW 96
#define kCh 256
#define kC 64
#define kL 9216          // 96*96
#define kNH 4
#define kHB 64           // hash buckets
#define kCHK 144
#define kTOTJ 36864      // kNH*kL
#define kJW 432          // 3*kCHK

// smem strides (attn)
#define QRS 68
#define KP2S 76          // float2 col stride for K pair layout
#define PU32S 44         // u32 stride for P bf16-pair rows (CF write + ldmatrix)
#define VSSU 132         // u32 stride for V bf16 rows (264 bf16; CF)
#define ATHR 576

// conv packed layouts
#define WYS 68           // uint2 row stride, conv bf16 weights (CF)

__device__ __forceinline__ unsigned pack_bf2(float lo, float hi) {
    __nv_bfloat162 t = __floats2bfloat162_rn(lo, hi);
    return *(unsigned*)&t;
}
__device__ __forceinline__ float bf_hi(float v) {
    return __bfloat162float(__float2bfloat16_rn(v));
}
__device__ __forceinline__ void mma_tf32(float* d, const unsigned* a, unsigned b0, unsigned b1) {
    asm("mma.sync.aligned.m16n8k8.row.col.f32.tf32.tf32.f32 "
        "{%0,%1,%2,%3},{%4,%5,%6,%7},{%8,%9},{%0,%1,%2,%3};"
        : "+f"(d[0]), "+f"(d[1]), "+f"(d[2]), "+f"(d[3])
        : "r"(a[0]), "r"(a[1]), "r"(a[2]), "r"(a[3]), "r"(b0), "r"(b1));
}
__device__ __forceinline__ void mma_bf16(float* d, const unsigned* a, unsigned b0, unsigned b1) {
    asm("mma.sync.aligned.m16n8k16.row.col.f32.bf16.bf16.f32 "
        "{%0,%1,%2,%3},{%4,%5,%6,%7},{%8,%9},{%0,%1,%2,%3};"
        : "+f"(d[0]), "+f"(d[1]), "+f"(d[2]), "+f"(d[3])
        : "r"(a[0]), "r"(a[1]), "r"(a[2]), "r"(a[3]), "r"(b0), "r"(b1));
}
__device__ __forceinline__ void ldm_x4(unsigned* r, unsigned saddr) {
    asm volatile("ldmatrix.sync.aligned.m8n8.x4.shared.b16 {%0,%1,%2,%3},[%4];"
        : "=r"(r[0]), "=r"(r[1]), "=r"(r[2]), "=r"(r[3]) : "r"(saddr));
}
__device__ __forceinline__ void ldm_x4t(unsigned* r, unsigned saddr) {
    asm volatile("ldmatrix.sync.aligned.m8n8.x4.trans.shared.b16 {%0,%1,%2,%3},[%4];"
        : "=r"(r[0]), "=r"(r[1]), "=r"(r[2]), "=r"(r[3]) : "r"(saddr));
}
__device__ __forceinline__ void cp16(void* dst, const void* src) {
    unsigned s = (unsigned)__cvta_generic_to_shared(dst);
    asm volatile("cp.async.cg.shared.global [%0],[%1],16;" :: "r"(s), "l"(src));
}
__device__ __forceinline__ void cp_commit() { asm volatile("cp.async.commit_group;"); }
__device__ __forceinline__ void cp_wait1() { asm volatile("cp.async.wait_group 1;"); }
__device__ __forceinline__ void cp_wait0() { asm volatile("cp.async.wait_group 0;"); }

// -------- scratch (device globals; no allocation allowed) --------
__device__ float g_x[(size_t)kN*kL*kC];            // x_embed (n,t,f)
__device__ __nv_bfloat16 g_yb[(size_t)kN*kL*kCh];  // y_embed bf16 (n,t,e)
__device__ int   g_codes[kN*kTOTJ];
__device__ int   g_sorted[kN*kTOTJ];
__device__ int   g_hist[kN*144*256];
__device__ unsigned g_retb[(size_t)kN*kNH*kL*kCh/2]; // attention out bf16 pairs
__device__ float g_bs[kN*kNH*kL];                  // lse (n,h,t)
// prepacked operands (bf16 hi/lo pair layouts for m16n8k16 fragments)
__device__ uint2  g_wybf[4*16*36*64];              // convy weights [cog][sl][r][nn]
__device__ uint2  g_wxbh[16*36*64];                // convx weights hi
__device__ uint2  g_wxbl[16*36*64];                // convx weights lo
__device__ uint2  g_inbf[(size_t)kN*kL*64];        // input hi pairs [pix][sl][kq]
__device__ uint2  g_inbl[(size_t)kN*kL*64];        // input lo pairs

// ---------------- prepack kernels ----------------
__global__ __launch_bounds__(256) void prep_inbf2_kernel(const float* __restrict__ in)
{
    size_t i = (size_t)blockIdx.x*256 + threadIdx.x;
    int kq = (int)(i & 3);
    int sl = (int)((i >> 2) & 15);
    size_t pix = i >> 6;
    const float* p = &in[pix*256 + sl*16 + 2*kq];
    float v0 = p[0], v1 = p[1], v8 = p[8], v9 = p[9];
    float h0 = bf_hi(v0), h1 = bf_hi(v1), h8 = bf_hi(v8), h9 = bf_hi(v9);
    uint2 oh, ol;
    oh.x = pack_bf2(h0, h1);        oh.y = pack_bf2(h8, h9);
    ol.x = pack_bf2(v0-h0, v1-h1);  ol.y = pack_bf2(v8-h8, v9-h9);
    g_inbf[i] = oh;
    g_inbl[i] = ol;
}

__global__ __launch_bounds__(256) void prep_wxbf_kernel(const float* __restrict__ w)
{
    int i = blockIdx.x*256 + threadIdx.x;              // < 36864
    int nn = i & 63;
    int r  = (i >> 6) % 36;
    int sl = i / 2304;
    int tap = r >> 2, kq = r & 3;
    int cin = sl*16 + 2*kq;
    const float* wp = &w[(tap*kCh + cin)*kC + nn];
    float w0 = wp[0], w1 = wp[kC], w8 = wp[8*kC], w9 = wp[9*kC];
    float h0 = bf_hi(w0), h1 = bf_hi(w1), h8 = bf_hi(w8), h9 = bf_hi(w9);
    uint2 oh, ol;
    oh.x = pack_bf2(h0, h1);        oh.y = pack_bf2(h8, h9);
    ol.x = pack_bf2(w0-h0, w1-h1);  ol.y = pack_bf2(w8-h8, w9-h9);
    g_wxbh[i] = oh;
    g_wxbl[i] = ol;
}

__global__ __launch_bounds__(256) void prep_wybf_kernel(const float* __restrict__ w)
{
    int i = blockIdx.x*256 + threadIdx.x;              // < 4*36864
    int nn = i & 63;
    int r  = (i >> 6) % 36;
    int sl = (i >> 6) / 36 % 16;
    int cog = i / 36864;
    int tap = r >> 2, kq = r & 3;
    int cin = sl*16 + 2*kq;
    const float* wp = &w[(size_t)(tap*kCh + cin)*kCh + cog*64 + nn];
    uint2 o;
    o.x = pack_bf2(wp[0], wp[kCh]);
    o.y = pack_bf2(wp[8*kCh], wp[9*kCh]);
    g_wybf[i] = o;
}

// ---------------- match conv (x path), bf16x2 3-product MMA, 3-stage pipe --
__global__ __launch_bounds__(512, 1) void convx_mma_kernel(const float* __restrict__ bias)
{
    extern __shared__ uint2 smc[];
    // per stage: pH(1296) pL(1296) wH(2448) wL(2448) = 7488 uint2
    uint2* pBh[3] = {smc,          smc + 7488,        smc + 14976};
    uint2* pBl[3] = {smc + 1296,   smc + 7488 + 1296, smc + 14976 + 1296};
    uint2* wBh[3] = {smc + 2592,   smc + 7488 + 2592, smc + 14976 + 2592};
    uint2* wBl[3] = {smc + 5040,   smc + 7488 + 5040, smc + 14976 + 5040};

    int n    = blockIdx.x / 36;
    int tile = blockIdx.x % 36;
    int by = (tile / 6) * 16, bx = (tile % 6) * 16;
    int tid = threadIdx.x;
    int wid = tid >> 5, lane = tid & 31;
    int m0w = (wid >> 1) * 32;
    int n0w = (wid & 1) * 32;
    int kq = lane & 3;
    int nq = lane >> 2;

    long long p_gidx[2];
#pragma unroll
    for (int i = 0; i < 2; i++) {
        int lin = tid + i*512;
        p_gidx[i] = -1;
        if (lin < 648) {
            int pos = lin >> 1;
            int yy = pos / 18, xx = pos % 18;
            int hh = by + yy - 1, ww = bx + xx - 1;
            if (hh >= 0 && hh < kH && ww >= 0 && ww < kW)
                p_gidx[i] = ((long long)((n*kH + hh)*kW + ww))*64 + (lin & 1)*2;
        }
    }
#pragma unroll
    for (int i = 0; i < 2; i++) {
        int lin = tid + i*512;
        if (lin < 648 && p_gidx[i] < 0) {
            uint2 z = {0u, 0u};
            int d = (lin >> 1)*4 + (lin & 1)*2;
#pragma unroll
            for (int s = 0; s < 3; s++) {
                pBh[s][d] = z; pBh[s][d+1] = z;
                pBl[s][d] = z; pBl[s][d+1] = z;
            }
        }
    }

    float acc[8][4];
#pragma unroll
    for (int i = 0; i < 8; i++)
#pragma unroll
        for (int j = 0; j < 4; j++) acc[i][j] = 0.f;

    int pb[4];
#pragma unroll
    for (int t = 0; t < 4; t++) {
        int m = m0w + t*8 + nq;
        pb[t] = (m >> 4)*18 + (m & 15);
    }

    auto stage = [&](int sl, int buf) {
#pragma unroll
        for (int i = 0; i < 2; i++) {
            int lin = tid + i*512;
            if (lin < 648 && p_gidx[i] >= 0) {
                int d = (lin >> 1)*4 + (lin & 1)*2;
                cp16(&pBh[buf][d], &g_inbf[p_gidx[i] + sl*4]);
                cp16(&pBl[buf][d], &g_inbl[p_gidx[i] + sl*4]);
            }
        }
#pragma unroll
        for (int i = 0; i < 3; i++) {
            int lin = tid + i*512;
            if (lin < 1152) {
                int idx = lin*2;
                int r = idx >> 6, nn = idx & 63;
                int d = r*WYS + nn;
                cp16(&wBh[buf][d], &g_wxbh[sl*2304 + idx]);
                cp16(&wBl[buf][d], &g_wxbl[sl*2304 + idx]);
            }
        }
    };

    __syncthreads();   // pad zeros visible before first stage overlaps
    stage(0, 0); cp_commit();
    stage(1, 1); cp_commit();
    for (int sl = 0; sl < 16; sl++) {
        int buf = sl % 3;
        if (sl < 15) cp_wait1(); else cp_wait0();
        __syncthreads();
        uint2* ph = pBh[buf]; uint2* pl = pBl[buf];
        uint2* wh = wBh[buf]; uint2* wl = wBl[buf];

#pragma unroll
        for (int tap = 0; tap < 9; tap++) {
            int posoff = (tap/3)*18 + (tap%3);
            uint2 hL0 = ph[(pb[0] + posoff)*4 + kq];
            uint2 hH0 = ph[(pb[1] + posoff)*4 + kq];
            uint2 hL1 = ph[(pb[2] + posoff)*4 + kq];
            uint2 hH1 = ph[(pb[3] + posoff)*4 + kq];
            uint2 lL0 = pl[(pb[0] + posoff)*4 + kq];
            uint2 lH0 = pl[(pb[1] + posoff)*4 + kq];
            uint2 lL1 = pl[(pb[2] + posoff)*4 + kq];
            uint2 lH1 = pl[(pb[3] + posoff)*4 + kq];
            unsigned A0h[4] = {hL0.x, hH0.x, hL0.y, hH0.y};
            unsigned A1h[4] = {hL1.x, hH1.x, hL1.y, hH1.y};
            unsigned A0l[4] = {lL0.x, lH0.x, lL0.y, lH0.y};
            unsigned A1l[4] = {lL1.x, lH1.x, lL1.y, lH1.y};
            int wr = (tap*4 + kq)*WYS + n0w + nq;
#pragma unroll
            for (int nt = 0; nt < 4; nt++) {
                uint2 bh = wh[wr + nt*8];
                uint2 bl = wl[wr + nt*8];
                mma_bf16(acc[nt],     A0h, bh.x, bh.y);
                mma_bf16(acc[nt],     A0h, bl.x, bl.y);
                mma_bf16(acc[nt],     A0l, bh.x, bh.y);
                mma_bf16(acc[4 + nt], A1h, bh.x, bh.y);
                mma_bf16(acc[4 + nt], A1h, bl.x, bl.y);
                mma_bf16(acc[4 + nt], A1l, bh.x, bh.y);
            }
        }
        if (sl < 14) { stage(sl + 2, (sl + 2) % 3); cp_commit(); }
    }

    // epilogue: scatter f32 to g_x embed layout (p = f*144 + t/64, c = t%64)
#pragma unroll
    for (int mt = 0; mt < 2; mt++) {
#pragma unroll
        for (int half = 0; half < 2; half++) {
            int m = m0w + mt*16 + half*8 + nq;
            int py = by + (m >> 4), px = bx + (m & 15);
            int p = py*kW + px;
            int f = p / 144, pm = p % 144;
#pragma unroll
            for (int nt = 0; nt < 4; nt++) {
                int c = n0w + nt*8 + 2*kq;
                float v0 = acc[mt*4 + nt][half*2]     + bias[c];
                float v1 = acc[mt*4 + nt][half*2 + 1] + bias[c+1];
                g_x[((size_t)n*kL + pm*64 + c    )*kC + f] = v0;
                g_x[((size_t)n*kL + pm*64 + c + 1)*kC + f] = v1;
            }
        }
    }
}

// ---------------- asm conv (y path), bf16 m16n8k16 MMA, 3-stage pipe -------
__global__ __launch_bounds__(512, 1) void convy_mma_kernel(const float* __restrict__ bias)
{
    extern __shared__ uint2 smy2[];
    // per stage: pB(1296) wB(2448) = 3744 uint2
    uint2* pB[3] = {smy2,         smy2 + 3744,        smy2 + 7488};
    uint2* wB[3] = {smy2 + 1296,  smy2 + 3744 + 1296, smy2 + 7488 + 1296};

    int n    = blockIdx.x / 36;
    int tile = blockIdx.x % 36;
    int by = (tile / 6) * 16, bx = (tile % 6) * 16;
    int cog = blockIdx.y;
    int co0 = cog * 64;
    int tid = threadIdx.x;
    int wid = tid >> 5, lane = tid & 31;
    int m0w = (wid >> 1) * 32;
    int n0w = (wid & 1) * 32;
    int kq = lane & 3;
    int nq = lane >> 2;

    long long p_gidx[2];
#pragma unroll
    for (int i = 0; i < 2; i++) {
        int lin = tid + i*512;
        p_gidx[i] = -1;
        if (lin < 648) {
            int pos = lin >> 1;
            int yy = pos / 18, xx = pos % 18;
            int hh = by + yy - 1, ww = bx + xx - 1;
            if (hh >= 0 && hh < kH && ww >= 0 && ww < kW)
                p_gidx[i] = ((long long)((n*kH + hh)*kW + ww))*64 + (lin & 1)*2;
        }
    }
#pragma unroll
    for (int i = 0; i < 2; i++) {
        int lin = tid + i*512;
        if (lin < 648 && p_gidx[i] < 0) {
            uint2 z = {0u, 0u};
            int d = (lin >> 1)*4 + (lin & 1)*2;
#pragma unroll
            for (int s = 0; s < 3; s++) { pB[s][d] = z; pB[s][d+1] = z; }
        }
    }

    float acc[8][4];
#pragma unroll
    for (int i = 0; i < 8; i++)
#pragma unroll
        for (int j = 0; j < 4; j++) acc[i][j] = 0.f;

    int pb[4];
#pragma unroll
    for (int t = 0; t < 4; t++) {
        int m = m0w + t*8 + nq;
        pb[t] = (m >> 4)*18 + (m & 15);
    }

    const uint2* wsrc = &g_wybf[cog*36864];

    auto stage = [&](int sl, int buf) {
#pragma unroll
        for (int i = 0; i < 2; i++) {
            int lin = tid + i*512;
            if (lin < 648 && p_gidx[i] >= 0)
                cp16(&pB[buf][(lin >> 1)*4 + (lin & 1)*2], &g_inbf[p_gidx[i] + sl*4]);
        }
#pragma unroll
        for (int i = 0; i < 3; i++) {
            int lin = tid + i*512;
            if (lin < 1152) {
                int idx = lin*2;
                int r = idx >> 6, nn = idx & 63;
                cp16(&wB[buf][r*WYS + nn], &wsrc[sl*2304 + idx]);
            }
        }
    };

    __syncthreads();
    stage(0, 0); cp_commit();
    stage(1, 1); cp_commit();
    for (int sl = 0; sl < 16; sl++) {
        int buf = sl % 3;
        if (sl < 15) cp_wait1(); else cp_wait0();
        __syncthreads();
        uint2* up2 = pB[buf];
        uint2* w2  = wB[buf];

#pragma unroll
        for (int tap = 0; tap < 9; tap++) {
            int posoff = (tap/3)*18 + (tap%3);
            uint2 aL0 = up2[(pb[0] + posoff)*4 + kq];
            uint2 aH0 = up2[(pb[1] + posoff)*4 + kq];
            uint2 aL1 = up2[(pb[2] + posoff)*4 + kq];
            uint2 aH1 = up2[(pb[3] + posoff)*4 + kq];
            unsigned A0[4] = {aL0.x, aH0.x, aL0.y, aH0.y};
            unsigned A1[4] = {aL1.x, aH1.x, aL1.y, aH1.y};
            int wr = (tap*4 + kq)*WYS + n0w + nq;
#pragma unroll
            for (int nt = 0; nt < 4; nt++) {
                uint2 bw = w2[wr + nt*8];
                mma_bf16(acc[nt],     A0, bw.x, bw.y);
                mma_bf16(acc[4 + nt], A1, bw.x, bw.y);
            }
        }
        if (sl < 14) { stage(sl + 2, (sl + 2) % 3); cp_commit(); }
    }

#pragma unroll
    for (int mt = 0; mt < 2; mt++) {
#pragma unroll
        for (int half = 0; half < 2; half++) {
            int m = m0w + mt*16 + half*8 + nq;
            int py = by + (m >> 4), px = bx + (m & 15);
            int p = py*kW + px;
            int e = p / 36, pm = p % 36;
#pragma unroll
            for (int nt = 0; nt < 4; nt++) {
                int c = co0 + n0w + nt*8 + 2*kq;
                float v0 = acc[mt*4 + nt][half*2]     + bias[c];
                float v1 = acc[mt*4 + nt][half*2 + 1] + bias[c+1];
                g_yb[((size_t)n*kL + pm*256 + c    )*kCh + e] = __float2bfloat16_rn(v0);
                g_yb[((size_t)n*kL + pm*256 + c + 1)*kCh + e] = __float2bfloat16_rn(v1);
            }
        }
    }
}

// ---------------- LSH hashing ----------------
__global__ __launch_bounds__(256) void hash_kernel(const float* __restrict__ rot)
{
    __shared__ float Rsm[8192];
    __shared__ float xrow[8][64];
    int tid = threadIdx.x;
    for (int lin = tid; lin < 8192; lin += 256) Rsm[lin] = rot[lin];
    int wid = tid >> 5, lane = tid & 31;
    int idx = blockIdx.x*8 + wid;
    int n = idx / kL, t = idx % kL;
    const float* xr = &g_x[((size_t)n*kL + t)*kC];
    xrow[wid][lane]      = xr[lane];
    xrow[wid][lane + 32] = xr[lane + 32];
    __syncthreads();
#pragma unroll
    for (int h = 0; h < 4; h++) {
        float s = 0.f;
#pragma unroll
        for (int f = 0; f < 64; f++) s += xrow[wid][f] * Rsm[f*128 + h*32 + lane];
        float bv; int bi;
        if (s >= -s) { bv = s;  bi = lane; }
        else         { bv = -s; bi = lane + 32; }
#pragma unroll
        for (int off = 16; off > 0; off >>= 1) {
            float ov = __shfl_xor_sync(0xffffffffu, bv, off);
            int   oi = __shfl_xor_sync(0xffffffffu, bi, off);
            if (ov > bv || (ov == bv && oi < bi)) { bv = ov; bi = oi; }
        }
        if (lane == 0) g_codes[n*kTOTJ + h*kL + t] = bi + h*kHB;
    }
}

// ---------------- stable counting sort (argsort) ----------------
__global__ __launch_bounds__(256) void sortA_kernel()
{
    __shared__ int hist[256];
    int b = blockIdx.x; int n = b / 144, blk = b % 144; int tid = threadIdx.x;
    hist[tid] = 0; __syncthreads();
    int code = g_codes[n*kTOTJ + blk*256 + tid];
    atomicAdd(&hist[code], 1);
    __syncthreads();
    g_hist[(n*144 + blk)*256 + tid] = hist[tid];
}

__global__ __launch_bounds__(256) void sortBC_kernel()
{
    __shared__ int scanbuf[256];
    __shared__ int comb[256];
    __shared__ int cs[256];
    int b = blockIdx.x; int n = b / 144, blk = b % 144; int v = threadIdx.x;

    int tot = 0, off = 0;
    const int* hb = &g_hist[n*144*256 + v];
    for (int bb = 0; bb < 144; bb++) {
        int hv = hb[bb*256];
        tot += hv;
        if (bb < blk) off += hv;
    }
    scanbuf[v] = tot;
    __syncthreads();
    for (int d = 1; d < 256; d <<= 1) {
        int y = (v >= d) ? scanbuf[v - d] : 0;
        __syncthreads();
        scanbuf[v] += y;
        __syncthreads();
    }
    comb[v] = (scanbuf[v] - tot) + off;
    int c = g_codes[n*kTOTJ + blk*256 + v];
    cs[v] = c;
    __syncthreads();
    int rank = 0;
    for (int j = 0; j < v; j++) rank += (cs[j] == c);
    g_sorted[n*kTOTJ + comb[c] + rank] = blk*256 + v;
}

// ---------------- fused chunk attention: tf32 QK + bf16 ldmatrix PV --------
// double-buffered K/V: ONE full sync + one pair-barrier per chunk iteration.
__global__ __launch_bounds__(ATHR, 1) void attn_kernel()
{
    extern __shared__ float sm[];
    float* Qr  = sm;                                       // 9792 floats
    float* Kp0 = Qr + 9792;                                // 4864 floats
    float* Kp1 = Kp0 + 4864;                               // 4864
    unsigned* vs0 = (unsigned*)(Kp1 + 4864);               // 80*VSSU u32
    unsigned* vs1 = vs0 + 80*VSSU;                         // 80*VSSU
    unsigned* psm_u32 = vs1 + 80*VSSU;                     // 144*PU32S
    float* m_r = (float*)(psm_u32 + 144*PU32S);            // 144
    float* rowsumA = m_r + 144;                            // 144
    float* rowsumB = rowsumA + 144;                        // 144
    int* tIdx = (int*)(rowsumB + 144);                     // 432

    float2* kp2b[2] = {(float2*)Kp0, (float2*)Kp1};
    unsigned* vsb[2] = {vs0, vs1};

    int g = blockIdx.x;
    int n = g >> 8, k = g & 255;
    int h = k >> 6, kl = k & 63;
    int tid = threadIdx.x;
    int wid = tid >> 5, lane = tid & 31;
    int kq = lane & 3, nq = lane >> 2;

    for (int j = tid; j < kJW; j += ATHR) {
        int cchunk = j / kCHK, i = j % kCHK;
        int skl = (cchunk == 0) ? kl : (cchunk == 1) ? ((kl + 63) & 63) : ((kl + 1) & 63);
        int s = (h*64 + skl)*kCHK + i;
        tIdx[j] = g_sorted[n*kTOTJ + s] % kL;
    }
    for (int i = tid; i < kCHK; i += ATHR) { rowsumA[i] = 0.f; rowsumB[i] = 0.f; }
    for (int i = tid; i < 144*8; i += ATHR)
        psm_u32[(i >> 3)*PU32S + 36 + (i & 7)] = 0u;
    for (int i = tid; i < 8*VSSU; i += ATHR) {
        vs0[72*VSSU + i] = 0u;
        vs1[72*VSSU + i] = 0u;
    }
    __syncthreads();

    {
#pragma unroll
        for (int rr = 0; rr < 8; rr++) {
            int r = wid*8 + rr;
            const float* xr = &g_x[((size_t)n*kL + tIdx[r])*kC];
            float a = xr[lane], b = xr[lane + 32];
            Qr[r*QRS + lane] = a;
            Qr[r*QRS + lane + 32] = b;
            float ss = a*a + b*b;
#pragma unroll
            for (int off = 16; off > 0; off >>= 1)
                ss += __shfl_xor_sync(0xffffffffu, ss, off);
            if (lane == 0) m_r[r] = ss * rsqrtf(fmaxf(ss, 5e-5f));
        }
    }
    // no sync needed here: the per-iteration sync below orders Qr/m_r before QK

    int wq = wid % 9;
    int halfq = wid / 9;
    int m0 = wq * 16;

    float Oacc[16][4];
#pragma unroll
    for (int i = 0; i < 16; i++)
#pragma unroll
        for (int j = 0; j < 4; j++) Oacc[i][j] = 0.f;

    unsigned pbase = (unsigned)__cvta_generic_to_shared(psm_u32);
    unsigned aaddr = pbase + (unsigned)((m0 + (lane & 15))*(PU32S*4) + (lane >> 4)*16);
    unsigned vb0 = (unsigned)__cvta_generic_to_shared(vs0);
    unsigned vb1 = (unsigned)__cvta_generic_to_shared(vs1);
    unsigned boff = (unsigned)((lane & 15)*(VSSU*4) + ((halfq*128 + (lane >> 4)*8) << 1));
    unsigned baddrb[2] = {vb0 + boff, vb1 + boff};

    float mA = 0.f, mB = 0.f;
    {   // m_r needs a sync before first use in QK; fold into first iteration below
    }

    for (int jc = 0; jc < 6; jc++) {
        int j0 = jc*72;
        int buf = jc & 1;
        if (wid < 9) {
            float2* kp2 = kp2b[buf];
            int col = wid*8 + (lane >> 2);
            int fq = lane & 3;
            int fs = fq * 16;
            const float4* xr = (const float4*)&g_x[((size_t)n*kL + tIdx[j0 + col])*kC + fs];
            float4 v0 = xr[0], v1 = xr[1], v2 = xr[2], v3 = xr[3];
            float ss = v0.x*v0.x + v0.y*v0.y + v0.z*v0.z + v0.w*v0.w
                     + v1.x*v1.x + v1.y*v1.y + v1.z*v1.z + v1.w*v1.w
                     + v2.x*v2.x + v2.y*v2.y + v2.z*v2.z + v2.w*v2.w
                     + v3.x*v3.x + v3.y*v3.y + v3.z*v3.z + v3.w*v3.w;
            ss += __shfl_xor_sync(0xffffffffu, ss, 1);
            ss += __shfl_xor_sync(0xffffffffu, ss, 2);
            float r = rsqrtf(fmaxf(ss, 5e-5f));
            int ks0 = fq * 2;
            float2 t0; t0.x = v0.x*r; t0.y = v1.x*r; kp2[((ks0)*4 + 0)*KP2S + col] = t0;
            float2 t1; t1.x = v0.y*r; t1.y = v1.y*r; kp2[((ks0)*4 + 1)*KP2S + col] = t1;
            float2 t2; t2.x = v0.z*r; t2.y = v1.z*r; kp2[((ks0)*4 + 2)*KP2S + col] = t2;
            float2 t3; t3.x = v0.w*r; t3.y = v1.w*r; kp2[((ks0)*4 + 3)*KP2S + col] = t3;
            float2 t4; t4.x = v2.x*r; t4.y = v3.x*r; kp2[((ks0+1)*4 + 0)*KP2S + col] = t4;
            float2 t5; t5.x = v2.y*r; t5.y = v3.y*r; kp2[((ks0+1)*4 + 1)*KP2S + col] = t5;
            float2 t6; t6.x = v2.z*r; t6.y = v3.z*r; kp2[((ks0+1)*4 + 2)*KP2S + col] = t6;
            float2 t7; t7.x = v2.w*r; t7.y = v3.w*r; kp2[((ks0+1)*4 + 3)*KP2S + col] = t7;
        } else {
            unsigned* vs = vsb[buf];
            int w2 = wid - 9;
#pragma unroll
            for (int r = 0; r < 8; r++) {
                int row = w2*8 + r;
                uint4 v = ((const uint4*)&g_yb[((size_t)n*kL + tIdx[j0 + row])*kCh])[lane];
                ((uint4*)vs)[row*(VSSU/4) + lane] = v;
            }
        }
        __syncthreads();
        if (jc == 0) { mA = m_r[m0 + nq]; mB = m_r[m0 + 8 + nq]; }

        // QK MMA (tf32) + exp + bf16 P pairs to smem
        {
            float2* kp2 = kp2b[buf];
            unsigned Af[8][4];
#pragma unroll
            for (int ks = 0; ks < 8; ks++) {
                const float* q0 = &Qr[(m0 + nq)*QRS + ks*8 + kq];
                const float* q1 = &Qr[(m0 + 8 + nq)*QRS + ks*8 + kq];
                Af[ks][0] = __float_as_uint(q0[0]);
                Af[ks][1] = __float_as_uint(q1[0]);
                Af[ks][2] = __float_as_uint(q0[4]);
                Af[ks][3] = __float_as_uint(q1[4]);
            }
            float s0 = 0.f, s1 = 0.f;
            int ntBeg = halfq ? 5 : 0;
            int ntEnd = halfq ? 9 : 5;
            for (int nt = ntBeg; nt < ntEnd; nt++) {
                float acc[4] = {0.f, 0.f, 0.f, 0.f};
#pragma unroll
                for (int ks = 0; ks < 8; ks++) {
                    float2 bp = kp2[(ks*4 + kq)*KP2S + nt*8 + nq];
                    mma_tf32(acc, Af[ks], __float_as_uint(bp.x), __float_as_uint(bp.y));
                }
                float e0 = __expf(acc[0] - mA), e1 = __expf(acc[1] - mA);
                float e2 = __expf(acc[2] - mB), e3 = __expf(acc[3] - mB);
                s0 += e0 + e1; s1 += e2 + e3;
                psm_u32[(m0 + nq)*PU32S + nt*4 + kq]     = pack_bf2(e0, e1);
                psm_u32[(m0 + 8 + nq)*PU32S + nt*4 + kq] = pack_bf2(e2, e3);
            }
            s0 += __shfl_xor_sync(0xffffffffu, s0, 1);
            s0 += __shfl_xor_sync(0xffffffffu, s0, 2);
            s1 += __shfl_xor_sync(0xffffffffu, s1, 1);
            s1 += __shfl_xor_sync(0xffffffffu, s1, 2);
            if (kq == 0) {
                float* rs = halfq ? rowsumB : rowsumA;
                rs[m0 + nq] += s0;
                rs[m0 + 8 + nq] += s1;
            }
        }
        // partner-pair barrier: warps (wq,0) and (wq,1) exchange P halves
        asm volatile("bar.sync %0, 64;" :: "r"(1 + wq) : "memory");

        // PV MMA (bf16 m16n8k16 via ldmatrix), 5 uniform k16 groups
        {
            unsigned baddr = baddrb[buf];
#pragma unroll
            for (int gg = 0; gg < 5; gg++) {
                unsigned A[4];
                ldm_x4(A, aaddr + gg*32);
#pragma unroll
                for (int np = 0; np < 8; np++) {
                    unsigned B[4];
                    ldm_x4t(B, baddr + gg*16*(VSSU*4) + np*32);
                    mma_bf16(Oacc[2*np],     A, B[0], B[1]);
                    mma_bf16(Oacc[2*np + 1], A, B[2], B[3]);
                }
            }
        }
        // no end-of-loop sync: next iteration stages into the other buffer;
        // its post-stage __syncthreads retires this iteration's PV readers.
    }
    __syncthreads();

    {
        int n0 = halfq * 128;
        int rA = m0 + nq, rB = rA + 8;
        float sumA = rowsumA[rA] + rowsumB[rA];
        float sumB = rowsumA[rB] + rowsumB[rB];
        float invA = 1.f / sumA;
        float invB = 1.f / sumB;
        size_t baseA = ((size_t)(n*4 + h)*kL + tIdx[rA])*kCh;
        size_t baseB = ((size_t)(n*4 + h)*kL + tIdx[rB])*kCh;
#pragma unroll
        for (int nt = 0; nt < 16; nt++) {
            int cA = n0 + nt*8 + 2*kq;
            g_retb[(baseA + cA) >> 1] = pack_bf2(Oacc[nt][0]*invA, Oacc[nt][1]*invA);
            g_retb[(baseB + cA) >> 1] = pack_bf2(Oacc[nt][2]*invB, Oacc[nt][3]*invB);
        }
        if (wid < 9 && lane < 16) {
            int row = wid*16 + lane;
            float s = rowsumA[row] + rowsumB[row];
            g_bs[(size_t)(n*4 + h)*kL + tIdx[row]] = m_r[row] + __logf(s);
        }
    }
}

// ---------------- head combine + residual + output layout ----------------
__global__ __launch_bounds__(256) void combine_kernel(
    const float* __restrict__ in, float* __restrict__ out)
{
    __shared__ float accs[256*33];
    __shared__ float probs[4*256];
    int n = blockIdx.x / 36, q = blockIdx.x % 36;
    int e0 = blockIdx.y * 32;
    int tid = threadIdx.x;

    {
        int t = q*256 + tid;
        float b0 = g_bs[(size_t)(n*4 + 0)*kL + t];
        float b1 = g_bs[(size_t)(n*4 + 1)*kL + t];
        float b2 = g_bs[(size_t)(n*4 + 2)*kL + t];
        float b3 = g_bs[(size_t)(n*4 + 3)*kL + t];
        float m = fmaxf(fmaxf(b0, b1), fmaxf(b2, b3));
        float x0 = __expf(b0 - m), x1 = __expf(b1 - m);
        float x2 = __expf(b2 - m), x3 = __expf(b3 - m);
        float sinv = 1.f / (x0 + x1 + x2 + x3);
        probs[0*256 + tid] = x0*sinv; probs[1*256 + tid] = x1*sinv;
        probs[2*256 + tid] = x2*sinv; probs[3*256 + tid] = x3*sinv;
    }
    for (int lin = tid; lin < 256*33; lin += 256) accs[lin] = 0.f;
    __syncthreads();

    for (int h = 0; h < 4; h++) {
        for (int lin = tid; lin < 256*16; lin += 256) {
            int cc = lin >> 4, ep = lin & 15;
            unsigned pv = g_retb[(((size_t)(n*4 + h)*kL + q*256 + cc)*kCh + e0) / 2 + ep];
            __nv_bfloat162 b = *(__nv_bfloat162*)&pv;
            float pr = probs[h*256 + cc];
            accs[cc*33 + 2*ep]     += pr * __low2float(b);
            accs[cc*33 + 2*ep + 1] += pr * __high2float(b);
        }
    }
    __syncthreads();

    for (int lin = tid; lin < 32*256; lin += 256) {
        int e = lin >> 8, c = lin & 255;
        int p = (e0 + e)*36 + q;
        size_t oi = ((size_t)n*kL + p)*kCh + c;
        out[oi] = 0.1f*accs[c*33 + e] + in[oi];
    }
}

// ---------------- launch: stream-forked (capture-safe fork/join) ----------
extern "C" void kernel_launch(void* const* d_in, const int* in_sizes, int n_in,
                              void* d_out, int out_size)
{
    const float* input     = (const float*)d_in[0];
    const float* w_match   = (const float*)d_in[1];
    const float* b_match   = (const float*)d_in[2];
    const float* w_asm     = (const float*)d_in[3];
    const float* b_asm     = (const float*)d_in[4];
    const float* rotations = (const float*)d_in[5];
    float* out = (float*)d_out;

    const int CONVX_SMEM = 22464 * 8;                                   // 179712
    const int CONVY_SMEM = 11232 * 8;                                   // 89856
    const int ATT_SMEM   = (9792 + 2*4864 + 2*80*VSSU + 144*PU32S + 144*3 + 432) * 4;

    static cudaStream_t sY = nullptr;
    static cudaEvent_t evFork = nullptr, evJoin = nullptr;
    if (sY == nullptr) {
        cudaStreamCreateWithFlags(&sY, cudaStreamNonBlocking);
        cudaEventCreateWithFlags(&evFork, cudaEventDisableTiming);
        cudaEventCreateWithFlags(&evJoin, cudaEventDisableTiming);
        cudaFuncSetAttribute(convx_mma_kernel, cudaFuncAttributeMaxDynamicSharedMemorySize, CONVX_SMEM);
        cudaFuncSetAttribute(convy_mma_kernel, cudaFuncAttributeMaxDynamicSharedMemorySize, CONVY_SMEM);
        cudaFuncSetAttribute(attn_kernel,      cudaFuncAttributeMaxDynamicSharedMemorySize, ATT_SMEM);
    }

    prep_inbf2_kernel<<<kN*kL*64/256, 256>>>(input);
    cudaEventRecord(evFork, 0);
    cudaStreamWaitEvent(sY, evFork, 0);

    prep_wxbf_kernel<<<144, 256>>>(w_match);                            // s0
    prep_wybf_kernel<<<576, 256, 0, sY>>>(w_asm);                       // sY
    convy_mma_kernel<<<dim3(kN*36, 4), 512, CONVY_SMEM, sY>>>(b_asm);   // sY (#4, ncu slot)
    cudaEventRecord(evJoin, sY);
    convx_mma_kernel<<<kN*36, 512, CONVX_SMEM>>>(b_match);              // s0
    hash_kernel<<<kN*kL/8, 256>>>(rotations);
    sortA_kernel<<<kN*144, 256>>>();
    sortBC_kernel<<<kN*144, 256>>>();
    cudaStreamWaitEvent(0, evJoin, 0);
    attn_kernel<<<kN*256, ATHR, ATT_SMEM>>>();
    combine_kernel<<<dim3(kN*36, 8), 256>>>(input, out);
}